// round 1
// baseline (speedup 1.0000x reference)
#include <cuda_runtime.h>
#include <cmath>

#define B_   256
#define DIN_ 1024
#define DG_  1024
#define U_   512
#define D_   16
#define M_   256   // memory slots == batch
#define G_   8

// scratch (device globals: allocation-free rule)
__device__ float g_h[B_ * DG_];                       // 1 MB: h = x@W1+b1
__device__ float g_w[(size_t)U_ * B_ * M_];           // 128 MB: weights in [U][B][M]

// ---------------------------------------------------------------------------
// Generic fp32 SGEMM with bias: C[M,N] = A[M,K] @ B[K,N] + bias[N]
// 256 threads, register tile TM x TN. All dims divide tiles exactly here.
// ---------------------------------------------------------------------------
template<int BM, int BN, int BK, int TM, int TN>
__global__ void __launch_bounds__(256) sgemm_bias(
        const float* __restrict__ A, const float* __restrict__ Bm,
        const float* __restrict__ bias, float* __restrict__ C,
        int M, int N, int K)
{
    __shared__ float As[BK][BM + 4];   // transposed A tile
    __shared__ float Bs[BK][BN];

    const int tid = threadIdx.x;
    const int bx = blockIdx.x, by = blockIdx.y;
    constexpr int TX = BN / TN;
    const int tx = tid % TX;
    const int ty = tid / TX;

    float acc[TM][TN];
#pragma unroll
    for (int r = 0; r < TM; r++)
#pragma unroll
        for (int c = 0; c < TN; c++) acc[r][c] = 0.f;

    constexpr int AF4 = BM * BK / 4;
    constexpr int BF4 = BK * BN / 4;
    constexpr int LA = AF4 / 256;
    constexpr int LB = BF4 / 256;
    static_assert(LA >= 1 && LB >= 1, "tile too small");

    const float* Ablk = A + (size_t)by * BM * K;
    const float* Bblk = Bm + (size_t)bx * BN;

    for (int k0 = 0; k0 < K; k0 += BK) {
#pragma unroll
        for (int i = 0; i < LA; i++) {
            int a = tid + i * 256;
            int row = a / (BK / 4);
            int kq  = a % (BK / 4);
            float4 v = *(const float4*)(Ablk + (size_t)row * K + k0 + kq * 4);
            As[kq*4+0][row] = v.x;
            As[kq*4+1][row] = v.y;
            As[kq*4+2][row] = v.z;
            As[kq*4+3][row] = v.w;
        }
#pragma unroll
        for (int i = 0; i < LB; i++) {
            int b = tid + i * 256;
            int kr = b / (BN / 4);
            int nq = b % (BN / 4);
            *(float4*)(&Bs[kr][nq*4]) =
                *(const float4*)(Bblk + (size_t)(k0 + kr) * N + nq * 4);
        }
        __syncthreads();

#pragma unroll
        for (int k = 0; k < BK; k++) {
            float ra[TM], rb[TN];
#pragma unroll
            for (int r = 0; r < TM; r++) ra[r] = As[k][ty*TM + r];
#pragma unroll
            for (int c = 0; c < TN; c += 4) {
                float4 v = *(const float4*)(&Bs[k][tx*TN + c]);
                rb[c+0] = v.x; rb[c+1] = v.y; rb[c+2] = v.z; rb[c+3] = v.w;
            }
#pragma unroll
            for (int r = 0; r < TM; r++)
#pragma unroll
                for (int c = 0; c < TN; c++)
                    acc[r][c] += ra[r] * rb[c];
        }
        __syncthreads();
    }

#pragma unroll
    for (int r = 0; r < TM; r++) {
        int row = by*BM + ty*TM + r;
#pragma unroll
        for (int c = 0; c < TN; c += 4) {
            int col = bx*BN + tx*TN + c;
            float4 v;
            v.x = acc[r][c+0] + bias[col+0];
            v.y = acc[r][c+1] + bias[col+1];
            v.z = acc[r][c+2] + bias[col+2];
            v.w = acc[r][c+3] + bias[col+3];
            *(float4*)(C + (size_t)row * N + col) = v;
        }
    }
}

// ---------------------------------------------------------------------------
// Fused per-(u, b-tile=64) kernel:
//   scores S[64,256] = attn_tile[64,16] @ Ma_u[256,16]^T  (temp scale, eye mask)
//   grouped softmax over m (groups m % 8), /8
//   write normalized weights to g_w[u][b][m]   (coalesced)
//   O[64,16] = S @ Mv_u[256,16] -> outputs[b,u,:]
// ---------------------------------------------------------------------------
#define SS_PITCH 264   // 64 rows, pad so stride-8 softmax reads are conflict-free
#define MA_PITCH 258
#define SM3_FLOATS (1024 + 16*MA_PITCH + 64*SS_PITCH + 4096)

__global__ void __launch_bounds__(256) attn_softmax_out_kernel(
        const float* __restrict__ attn,   // [B,U,D]
        const float* __restrict__ Ma,     // [M,U,D]
        const float* __restrict__ Mv,     // [M,U,D]
        const float* __restrict__ temp,   // [U]
        float* __restrict__ outp)         // [B,U,D]
{
    extern __shared__ float sm[];
    float* sA   = sm;                         // 64 x 16
    float* sMaT = sm + 1024;                  // 16 x 258  (d-major, m inner)
    float* sS   = sMaT + 16 * MA_PITCH;       // 64 x 264
    float* sMv  = sS + 64 * SS_PITCH;         // 256 x 16

    const int u   = blockIdx.x;
    const int b0  = blockIdx.y * 64;
    const int tid = threadIdx.x;

    // ---- load tiles ----
    {
        int i = tid >> 2, dq = tid & 3;       // 64 rows x 4 float4
        *(float4*)(sA + i*16 + dq*4) =
            *(const float4*)(attn + ((size_t)(b0 + i)*U_ + u)*D_ + dq*4);
    }
#pragma unroll
    for (int t = 0; t < 4; t++) {
        int idx = tid + t * 256;              // 1024 float4
        int m = idx >> 2, dq = idx & 3;
        float4 v = *(const float4*)(Ma + ((size_t)m*U_ + u)*D_ + dq*4);
        sMaT[(dq*4+0)*MA_PITCH + m] = v.x;
        sMaT[(dq*4+1)*MA_PITCH + m] = v.y;
        sMaT[(dq*4+2)*MA_PITCH + m] = v.z;
        sMaT[(dq*4+3)*MA_PITCH + m] = v.w;
        *(float4*)(sMv + m*16 + dq*4) =
            *(const float4*)(Mv + ((size_t)m*U_ + u)*D_ + dq*4);
    }
    const float tu = temp[u];
    __syncthreads();

    // ---- stage 1: scores (8x8 register tile; warp = one ty -> sA broadcast,
    //               sMaT reads consecutive in tx -> conflict-free) ----
    const int tx = tid & 31;   // m = tx + 32*c
    const int ty = tid >> 5;   // b rows ty*8 .. ty*8+7
    float acc[8][8];
#pragma unroll
    for (int r = 0; r < 8; r++)
#pragma unroll
        for (int c = 0; c < 8; c++) acc[r][c] = 0.f;

#pragma unroll
    for (int k = 0; k < 16; k++) {
        float ra[8], rb[8];
#pragma unroll
        for (int r = 0; r < 8; r++) ra[r] = sA[(ty*8 + r)*16 + k];
#pragma unroll
        for (int c = 0; c < 8; c++) rb[c] = sMaT[k*MA_PITCH + tx + 32*c];
#pragma unroll
        for (int r = 0; r < 8; r++)
#pragma unroll
            for (int c = 0; c < 8; c++)
                acc[r][c] += ra[r] * rb[c];
    }

#pragma unroll
    for (int r = 0; r < 8; r++) {
        int bl = ty*8 + r;
        int bg = b0 + bl;
#pragma unroll
        for (int c = 0; c < 8; c++) {
            int m = tx + 32*c;
            float s = acc[r][c] * tu;
            sS[bl*SS_PITCH + m] = (m == bg) ? -INFINITY : s;
        }
    }
    __syncthreads();

    // ---- stage 2: grouped softmax over m within (b, m%8), then /8 ----
#pragma unroll
    for (int gi = 0; gi < 2; gi++) {
        int g = tid + gi * 256;               // 512 groups = 64 b x 8 residues
        float* row = sS + (g >> 3) * SS_PITCH + (g & 7);
        float v[32];
        float mx = -INFINITY;
#pragma unroll
        for (int k = 0; k < 32; k++) { v[k] = row[k*8]; mx = fmaxf(mx, v[k]); }
        float s = 0.f;
#pragma unroll
        for (int k = 0; k < 32; k++) { v[k] = __expf(v[k] - mx); s += v[k]; }
        float inv = 1.f / (8.f * s);
#pragma unroll
        for (int k = 0; k < 32; k++) row[k*8] = v[k] * inv;
    }
    __syncthreads();

    // ---- stage 2b: coalesced dump of normalized weights to g_w[u][b][m] ----
    float* wrow = g_w + (size_t)u * (B_ * M_) + (size_t)b0 * M_;
#pragma unroll
    for (int t = 0; t < 16; t++) {
        int idx = tid + t * 256;              // 4096 float4
        int bl = idx >> 6;
        int mq = idx & 63;
        float4 v = *(float4*)(sS + bl*SS_PITCH + mq*4);
        *(float4*)(wrow + (size_t)bl * M_ + mq*4) = v;
    }

    // ---- stage 3: outputs O[64,16] = W[64,256] @ Mv[256,16] ----
    const int bl = tid >> 2;
    const int dq = tid & 3;
    const float* srow = sS + bl * SS_PITCH;
    float4 o = make_float4(0.f, 0.f, 0.f, 0.f);
#pragma unroll 8
    for (int m = 0; m < 256; m++) {
        float w = srow[m];
        float4 mv = *(const float4*)(sMv + m*16 + dq*4);
        o.x += w * mv.x; o.y += w * mv.y; o.z += w * mv.z; o.w += w * mv.w;
    }
    *(float4*)(outp + ((size_t)(b0 + bl)*U_ + u)*D_ + dq*4) = o;
}

// ---------------------------------------------------------------------------
// Transpose g_w [U][B][M] -> weights [B][M][U], 32x32 smem tiles.
// ---------------------------------------------------------------------------
__global__ void __launch_bounds__(256) transpose_uw(float* __restrict__ wout)
{
    __shared__ float t[32][33];
    const int m0 = blockIdx.x * 32;
    const int u0 = blockIdx.y * 32;
    const int b  = blockIdx.z;
    const int x = threadIdx.x;
    const int y = threadIdx.y;
#pragma unroll
    for (int s = 0; s < 4; s++) {
        int uu = u0 + y + 8*s;
        t[y + 8*s][x] = g_w[((size_t)uu * B_ + b) * M_ + m0 + x];
    }
    __syncthreads();
#pragma unroll
    for (int s = 0; s < 4; s++) {
        int mm = m0 + y + 8*s;
        wout[((size_t)b * M_ + mm) * U_ + u0 + x] = t[x][y + 8*s];
    }
}

// ---------------------------------------------------------------------------
extern "C" void kernel_launch(void* const* d_in, const int* in_sizes, int n_in,
                              void* d_out, int out_size)
{
    const float* x    = (const float*)d_in[0];
    const float* W1   = (const float*)d_in[1];
    const float* b1   = (const float*)d_in[2];
    const float* W2   = (const float*)d_in[3];
    const float* b2   = (const float*)d_in[4];
    const float* temp = (const float*)d_in[5];
    const float* Ma   = (const float*)d_in[6];
    const float* Mv   = (const float*)d_in[7];

    float* attn = (float*)d_out;                         // [B,U,D]
    float* wout = attn + (size_t)B_ * U_ * D_;           // [B,M,U]
    float* outp = wout + (size_t)B_ * B_ * U_;           // [B,U,D]

    float* h_ptr = nullptr;
    cudaGetSymbolAddress((void**)&h_ptr, g_h);

    // h = x @ W1 + b1
    sgemm_bias<64, 64, 16, 4, 4><<<dim3(DG_/64, B_/64), 256>>>(
        x, W1, b1, h_ptr, B_, DG_, DIN_);

    // attention = h @ W2 + b2
    sgemm_bias<64, 128, 16, 4, 8><<<dim3((U_*D_)/128, B_/64), 256>>>(
        h_ptr, W2, b2, attn, B_, U_*D_, DG_);

    // fused scores + softmax + outputs (+ weights scratch)
    int smem3 = SM3_FLOATS * (int)sizeof(float);
    cudaFuncSetAttribute(attn_softmax_out_kernel,
                         cudaFuncAttributeMaxDynamicSharedMemorySize, smem3);
    attn_softmax_out_kernel<<<dim3(U_, B_/64), 256, smem3>>>(
        attn, Ma, Mv, temp, outp);

    // weights: [U][B][M] -> [B][M][U]
    transpose_uw<<<dim3(M_/32, U_/32, B_), dim3(32, 8)>>>(wout);
}

// round 2
// speedup vs baseline: 1.1124x; 1.1124x over previous
#include <cuda_runtime.h>
#include <cmath>

#define B_   256
#define DIN_ 1024
#define DG_  1024
#define U_   512
#define D_   16
#define M_   256
#define G_   8

#define NCHUNK 4
#define U_C   (U_ / NCHUNK)   // 128 u's per chunk

// scratch (device globals: allocation-free rule)
__device__ float g_h[B_ * DG_];                          // 1 MB
__device__ float g_w[(size_t)U_C * B_ * M_];             // 33.5 MB chunk scratch [u_local][b][m]

// ---------------------------------------------------------------------------
// f32x2 packed-FMA helpers (Blackwell dual-lane fp32)
// ---------------------------------------------------------------------------
__device__ __forceinline__ unsigned long long pk2(float a, float b) {
    unsigned long long r;
    asm("mov.b64 %0, {%1, %2};" : "=l"(r) : "f"(a), "f"(b));
    return r;
}
__device__ __forceinline__ void upk2(unsigned long long v, float& a, float& b) {
    asm("mov.b64 {%0, %1}, %2;" : "=f"(a), "=f"(b) : "l"(v));
}
__device__ __forceinline__ void ffma2(unsigned long long& d,
                                      unsigned long long a, unsigned long long b) {
    asm("fma.rn.f32x2 %0, %1, %2, %0;" : "+l"(d) : "l"(a), "l"(b));
}

// ---------------------------------------------------------------------------
// fp32 SGEMM with bias, f32x2 inner product: C[M,N] = A[M,K] @ B[K,N] + bias
// ---------------------------------------------------------------------------
template<int BM, int BN, int BK, int TM, int TN, int THREADS>
__global__ void __launch_bounds__(THREADS) sgemm_bias(
        const float* __restrict__ A, const float* __restrict__ Bm,
        const float* __restrict__ bias, float* __restrict__ C,
        int M, int N, int K)
{
    __shared__ float As[BK][BM + 4];   // k-major, m contiguous
    __shared__ float Bs[BK][BN];

    const int tid = threadIdx.x;
    const int bx = blockIdx.x, by = blockIdx.y;
    constexpr int TX = BN / TN;
    const int tx = tid % TX;
    const int ty = tid / TX;

    constexpr int LA = (BM * BK / 4) / THREADS;
    constexpr int LB = (BK * BN / 4) / THREADS;
    static_assert(LA >= 1 && LB >= 1, "tile too small");

    unsigned long long acc2[TM / 2][TN];
#pragma unroll
    for (int r = 0; r < TM / 2; r++)
#pragma unroll
        for (int c = 0; c < TN; c++) acc2[r][c] = 0ull;

    const float* Ablk = A + (size_t)by * BM * K;
    const float* Bblk = Bm + (size_t)bx * BN;

    // ---- initial tile load ----
    {
#pragma unroll
        for (int i = 0; i < LA; i++) {
            int a = tid + i * THREADS;
            int row = a / (BK / 4);
            int kq  = a % (BK / 4);
            float4 v = *(const float4*)(Ablk + (size_t)row * K + kq * 4);
            As[kq*4+0][row] = v.x; As[kq*4+1][row] = v.y;
            As[kq*4+2][row] = v.z; As[kq*4+3][row] = v.w;
        }
#pragma unroll
        for (int i = 0; i < LB; i++) {
            int b = tid + i * THREADS;
            int kr = b / (BN / 4);
            int nq = b % (BN / 4);
            *(float4*)(&Bs[kr][nq*4]) =
                *(const float4*)(Bblk + (size_t)kr * N + nq * 4);
        }
    }
    __syncthreads();

    for (int k0 = 0; k0 < K; k0 += BK) {
        // prefetch next tile into registers
        float4 nA[LA], nB[LB];
        const bool more = (k0 + BK) < K;
        if (more) {
#pragma unroll
            for (int i = 0; i < LA; i++) {
                int a = tid + i * THREADS;
                int row = a / (BK / 4);
                int kq  = a % (BK / 4);
                nA[i] = *(const float4*)(Ablk + (size_t)row * K + k0 + BK + kq * 4);
            }
#pragma unroll
            for (int i = 0; i < LB; i++) {
                int b = tid + i * THREADS;
                int kr = b / (BN / 4);
                int nq = b % (BN / 4);
                nB[i] = *(const float4*)(Bblk + (size_t)(k0 + BK + kr) * N + nq * 4);
            }
        }

        // compute
#pragma unroll
        for (int k = 0; k < BK; k++) {
            float av[TM], bv[TN];
#pragma unroll
            for (int q = 0; q < TM / 4; q++) {
                float4 v = *(const float4*)(&As[k][ty*TM + q*4]);
                av[q*4+0] = v.x; av[q*4+1] = v.y; av[q*4+2] = v.z; av[q*4+3] = v.w;
            }
#pragma unroll
            for (int q = 0; q < TN / 4; q++) {
                float4 v = *(const float4*)(&Bs[k][tx*TN + q*4]);
                bv[q*4+0] = v.x; bv[q*4+1] = v.y; bv[q*4+2] = v.z; bv[q*4+3] = v.w;
            }
            unsigned long long ra2[TM / 2], rbd[TN];
#pragma unroll
            for (int r = 0; r < TM / 2; r++) ra2[r] = pk2(av[2*r], av[2*r+1]);
#pragma unroll
            for (int c = 0; c < TN; c++) rbd[c] = pk2(bv[c], bv[c]);
#pragma unroll
            for (int r = 0; r < TM / 2; r++)
#pragma unroll
                for (int c = 0; c < TN; c++)
                    ffma2(acc2[r][c], ra2[r], rbd[c]);
        }

        if (more) {
            __syncthreads();
#pragma unroll
            for (int i = 0; i < LA; i++) {
                int a = tid + i * THREADS;
                int row = a / (BK / 4);
                int kq  = a % (BK / 4);
                As[kq*4+0][row] = nA[i].x; As[kq*4+1][row] = nA[i].y;
                As[kq*4+2][row] = nA[i].z; As[kq*4+3][row] = nA[i].w;
            }
#pragma unroll
            for (int i = 0; i < LB; i++) {
                int b = tid + i * THREADS;
                int kr = b / (BN / 4);
                int nq = b % (BN / 4);
                *(float4*)(&Bs[kr][nq*4]) = nB[i];
            }
            __syncthreads();
        }
    }

    // ---- epilogue ----
#pragma unroll
    for (int r2 = 0; r2 < TM / 2; r2++) {
        float s[2][TN];
#pragma unroll
        for (int c = 0; c < TN; c++) upk2(acc2[r2][c], s[0][c], s[1][c]);
#pragma unroll
        for (int h = 0; h < 2; h++) {
            int row = by*BM + ty*TM + 2*r2 + h;
#pragma unroll
            for (int c = 0; c < TN; c += 4) {
                int col = bx*BN + tx*TN + c;
                float4 v;
                v.x = s[h][c+0] + bias[col+0];
                v.y = s[h][c+1] + bias[col+1];
                v.z = s[h][c+2] + bias[col+2];
                v.w = s[h][c+3] + bias[col+3];
                *(float4*)(C + (size_t)row * N + col) = v;
            }
        }
    }
}

// ---------------------------------------------------------------------------
// Fused per-(u, b-tile=64): scores -> grouped softmax -> scratch dump -> output
// ---------------------------------------------------------------------------
#define SS_PITCH 264
#define MA_PITCH 258
#define SA_PITCH 68
#define SM3_FLOATS (16*SA_PITCH + 16*MA_PITCH + 64*SS_PITCH + 4096)

__global__ void __launch_bounds__(256) attn_softmax_out_kernel(
        const float* __restrict__ attn,   // [B,U,D]
        const float* __restrict__ Ma,     // [M,U,D]
        const float* __restrict__ Mv,     // [M,U,D]
        const float* __restrict__ temp,   // [U]
        float* __restrict__ outp,         // [B,U,D]
        int u0)
{
    extern __shared__ float sm[];
    float* sAT  = sm;                          // 16 x 68   (d-major, b inner)
    float* sMaT = sAT + 16 * SA_PITCH;         // 16 x 258  (d-major, m inner)
    float* sS   = sMaT + 16 * MA_PITCH;        // 64 x 264
    float* sMv  = sS + 64 * SS_PITCH;          // 256 x 16

    const int ul  = blockIdx.x;                // chunk-local u
    const int u   = u0 + ul;
    const int b0  = blockIdx.y * 64;
    const int tid = threadIdx.x;

    // ---- load tiles ----
    {
        int i = tid >> 2, dq = tid & 3;        // 64 b-rows x 4 float4
        float4 v = *(const float4*)(attn + ((size_t)(b0 + i)*U_ + u)*D_ + dq*4);
        sAT[(dq*4+0)*SA_PITCH + i] = v.x;
        sAT[(dq*4+1)*SA_PITCH + i] = v.y;
        sAT[(dq*4+2)*SA_PITCH + i] = v.z;
        sAT[(dq*4+3)*SA_PITCH + i] = v.w;
    }
#pragma unroll
    for (int t = 0; t < 4; t++) {
        int idx = tid + t * 256;
        int m = idx >> 2, dq = idx & 3;
        float4 v = *(const float4*)(Ma + ((size_t)m*U_ + u)*D_ + dq*4);
        sMaT[(dq*4+0)*MA_PITCH + m] = v.x;
        sMaT[(dq*4+1)*MA_PITCH + m] = v.y;
        sMaT[(dq*4+2)*MA_PITCH + m] = v.z;
        sMaT[(dq*4+3)*MA_PITCH + m] = v.w;
        *(float4*)(sMv + m*16 + dq*4) =
            *(const float4*)(Mv + ((size_t)m*U_ + u)*D_ + dq*4);
    }
    const float tu = temp[u];
    __syncthreads();

    // ---- stage 1: scores, f32x2 8x8 register tile ----
    const int tx = tid & 31;   // m = tx + 32*c
    const int ty = tid >> 5;   // b rows ty*8 .. ty*8+7
    unsigned long long acc2[4][8];
#pragma unroll
    for (int r = 0; r < 4; r++)
#pragma unroll
        for (int c = 0; c < 8; c++) acc2[r][c] = 0ull;

#pragma unroll
    for (int k = 0; k < 16; k++) {
        float4 a0 = *(const float4*)(&sAT[k*SA_PITCH + ty*8]);
        float4 a1 = *(const float4*)(&sAT[k*SA_PITCH + ty*8 + 4]);
        unsigned long long ra2[4];
        ra2[0] = pk2(a0.x, a0.y); ra2[1] = pk2(a0.z, a0.w);
        ra2[2] = pk2(a1.x, a1.y); ra2[3] = pk2(a1.z, a1.w);
        unsigned long long rbd[8];
#pragma unroll
        for (int c = 0; c < 8; c++) {
            float b = sMaT[k*MA_PITCH + tx + 32*c];
            rbd[c] = pk2(b, b);
        }
#pragma unroll
        for (int r = 0; r < 4; r++)
#pragma unroll
            for (int c = 0; c < 8; c++)
                ffma2(acc2[r][c], ra2[r], rbd[c]);
    }

#pragma unroll
    for (int r2 = 0; r2 < 4; r2++) {
#pragma unroll
        for (int c = 0; c < 8; c++) {
            float s0, s1;
            upk2(acc2[r2][c], s0, s1);
            int m  = tx + 32*c;
            int bl = ty*8 + 2*r2;
            sS[bl*SS_PITCH + m]     = (m == b0 + bl)     ? -INFINITY : s0 * tu;
            sS[(bl+1)*SS_PITCH + m] = (m == b0 + bl + 1) ? -INFINITY : s1 * tu;
        }
    }
    __syncthreads();

    // ---- stage 2: grouped softmax over m within (b, m%8), /8 ----
#pragma unroll
    for (int gi = 0; gi < 2; gi++) {
        int g = tid + gi * 256;
        float* row = sS + (g >> 3) * SS_PITCH + (g & 7);
        float v[32];
        float mx = -INFINITY;
#pragma unroll
        for (int k = 0; k < 32; k++) { v[k] = row[k*8]; mx = fmaxf(mx, v[k]); }
        float s = 0.f;
#pragma unroll
        for (int k = 0; k < 32; k++) { v[k] = __expf(v[k] - mx); s += v[k]; }
        float inv = 1.f / (8.f * s);
#pragma unroll
        for (int k = 0; k < 32; k++) row[k*8] = v[k] * inv;
    }
    __syncthreads();

    // ---- stage 2b: coalesced dump to g_w[ul][b][m] ----
    float* wrow = g_w + (size_t)ul * (B_ * M_) + (size_t)b0 * M_;
#pragma unroll
    for (int t = 0; t < 16; t++) {
        int idx = tid + t * 256;
        int bl = idx >> 6;
        int mq = idx & 63;
        float4 v = *(float4*)(sS + bl*SS_PITCH + mq*4);
        *(float4*)(wrow + (size_t)bl * M_ + mq*4) = v;
    }

    // ---- stage 3: O[64,16] = W[64,256] @ Mv[256,16], f32x2 ----
    const int bl = tid >> 2;
    const int dq = tid & 3;
    const float* srow = sS + bl * SS_PITCH;
    unsigned long long o2[2] = {0ull, 0ull};
#pragma unroll 4
    for (int m = 0; m < 256; m++) {
        float w = srow[m];
        unsigned long long wd = pk2(w, w);
        float4 mv = *(const float4*)(sMv + m*16 + dq*4);
        ffma2(o2[0], wd, pk2(mv.x, mv.y));
        ffma2(o2[1], wd, pk2(mv.z, mv.w));
    }
    float4 o;
    upk2(o2[0], o.x, o.y);
    upk2(o2[1], o.z, o.w);
    *(float4*)(outp + ((size_t)(b0 + bl)*U_ + u)*D_ + dq*4) = o;
}

// ---------------------------------------------------------------------------
// Transpose g_w [u_local][B][M] -> weights [B][M][U] (one 128-u chunk).
// 32x32 tiles, 128-bit on both global sides.
// ---------------------------------------------------------------------------
__global__ void __launch_bounds__(256) transpose_uw(float* __restrict__ wout, int u0)
{
    __shared__ float t[32][36];
    const int m0 = blockIdx.x * 32;
    const int ut = blockIdx.y * 32;   // chunk-local u base
    const int b  = blockIdx.z;
    const int tid = threadIdx.x;

    {
        int ur = tid >> 3;            // 0..31
        int mq = tid & 7;             // 0..7
        int lu = ut + ur;
        float4 v = __ldcs((const float4*)(g_w + ((size_t)lu * B_ + b) * M_ + m0 + mq*4));
        t[ur][mq*4+0] = v.x; t[ur][mq*4+1] = v.y;
        t[ur][mq*4+2] = v.z; t[ur][mq*4+3] = v.w;
    }
    __syncthreads();
    {
        int mr = tid >> 3;            // 0..31
        int uq = tid & 7;             // 0..7
        float4 v;
        v.x = t[uq*4+0][mr]; v.y = t[uq*4+1][mr];
        v.z = t[uq*4+2][mr]; v.w = t[uq*4+3][mr];
        *(float4*)(wout + ((size_t)b * M_ + m0 + mr) * U_ + u0 + ut + uq*4) = v;
    }
}

// ---------------------------------------------------------------------------
extern "C" void kernel_launch(void* const* d_in, const int* in_sizes, int n_in,
                              void* d_out, int out_size)
{
    const float* x    = (const float*)d_in[0];
    const float* W1   = (const float*)d_in[1];
    const float* b1   = (const float*)d_in[2];
    const float* W2   = (const float*)d_in[3];
    const float* b2   = (const float*)d_in[4];
    const float* temp = (const float*)d_in[5];
    const float* Ma   = (const float*)d_in[6];
    const float* Mv   = (const float*)d_in[7];

    float* attn = (float*)d_out;                         // [B,U,D]
    float* wout = attn + (size_t)B_ * U_ * D_;           // [B,M,U]
    float* outp = wout + (size_t)B_ * B_ * U_;           // [B,U,D]

    float* h_ptr = nullptr;
    cudaGetSymbolAddress((void**)&h_ptr, g_h);

    // h = x @ W1 + b1       (128 blocks of 128 threads)
    sgemm_bias<64, 32, 16, 4, 4, 128><<<dim3(DG_/32, B_/64), 128>>>(
        x, W1, b1, h_ptr, B_, DG_, DIN_);

    // attention = h @ W2 + b2   (128 blocks of 256 threads)
    sgemm_bias<128, 128, 16, 8, 8, 256><<<dim3((U_*D_)/128, B_/128), 256>>>(
        h_ptr, W2, b2, attn, B_, U_*D_, DG_);

    int smem3 = SM3_FLOATS * (int)sizeof(float);
    cudaFuncSetAttribute(attn_softmax_out_kernel,
                         cudaFuncAttributeMaxDynamicSharedMemorySize, smem3);

    // chunked: fused writes 33.5MB scratch, transpose consumes it from L2
    for (int c = 0; c < NCHUNK; c++) {
        int u0 = c * U_C;
        attn_softmax_out_kernel<<<dim3(U_C, B_/64), 256, smem3>>>(
            attn, Ma, Mv, temp, outp, u0);
        transpose_uw<<<dim3(M_/32, U_C/32, B_), 256>>>(wout, u0);
    }
}

// round 4
// speedup vs baseline: 1.1367x; 1.0219x over previous
#include <cuda_runtime.h>
#include <cmath>

#define B_   256
#define DIN_ 1024
#define DG_  1024
#define U_   512
#define D_   16
#define M_   256
#define G_   8

#define NB 16     // b per fused block
#define NU 8      // u per fused block
#define SP 264    // S pitch (floats)

__device__ float g_h[B_ * DG_];   // 1 MB scratch for h

// ---------------------------------------------------------------------------
// f32x2 helpers
// ---------------------------------------------------------------------------
typedef unsigned long long ull;
union F4U { float4 f; ull p[2]; float s[4]; };

__device__ __forceinline__ ull pk2(float a, float b) {
    ull r; asm("mov.b64 %0, {%1, %2};" : "=l"(r) : "f"(a), "f"(b)); return r;
}
__device__ __forceinline__ void upk2(ull v, float& a, float& b) {
    asm("mov.b64 {%0, %1}, %2;" : "=f"(a), "=f"(b) : "l"(v));
}
__device__ __forceinline__ void ffma2(ull& d, ull a, ull b) {
    asm("fma.rn.f32x2 %0, %1, %2, %0;" : "+l"(d) : "l"(a), "l"(b));
}
__device__ __forceinline__ ull add2(ull a, ull b) {
    ull r; asm("add.rn.f32x2 %0, %1, %2;" : "=l"(r) : "l"(a), "l"(b)); return r;
}

// ---------------------------------------------------------------------------
// fp32 SGEMM + bias, packed-pair inner product.
// REQUIREMENT: (BN/TN) * (BM/TM) == THREADS.
// ---------------------------------------------------------------------------
template<int BM, int BN, int BK, int TM, int TN, int THREADS>
__global__ void __launch_bounds__(THREADS) sgemm_bias(
        const float* __restrict__ A, const float* __restrict__ Bm,
        const float* __restrict__ bias, float* __restrict__ C,
        int M, int N, int K)
{
    static_assert((BN / TN) * (BM / TM) == THREADS, "thread tiling mismatch");
    __shared__ float As[BK][BM + 4];
    __shared__ float Bs[BK][BN];

    const int tid = threadIdx.x;
    const int bx = blockIdx.x, by = blockIdx.y;
    constexpr int TX = BN / TN;
    const int tx = tid % TX;
    const int ty = tid / TX;

    constexpr int LA = (BM * BK / 4) / THREADS;
    constexpr int LB = (BK * BN / 4) / THREADS;
    static_assert(LA >= 1 && LB >= 1, "tile too small");

    ull acc2[TM / 2][TN];
#pragma unroll
    for (int r = 0; r < TM / 2; r++)
#pragma unroll
        for (int c = 0; c < TN; c++) acc2[r][c] = 0ull;

    const float* Ablk = A + (size_t)by * BM * K;
    const float* Bblk = Bm + (size_t)bx * BN;

#pragma unroll
    for (int i = 0; i < LA; i++) {
        int a = tid + i * THREADS;
        int row = a / (BK / 4), kq = a % (BK / 4);
        float4 v = *(const float4*)(Ablk + (size_t)row * K + kq * 4);
        As[kq*4+0][row] = v.x; As[kq*4+1][row] = v.y;
        As[kq*4+2][row] = v.z; As[kq*4+3][row] = v.w;
    }
#pragma unroll
    for (int i = 0; i < LB; i++) {
        int b = tid + i * THREADS;
        int kr = b / (BN / 4), nq = b % (BN / 4);
        *(float4*)(&Bs[kr][nq*4]) = *(const float4*)(Bblk + (size_t)kr * N + nq * 4);
    }
    __syncthreads();

    for (int k0 = 0; k0 < K; k0 += BK) {
        float4 nA[LA], nB[LB];
        const bool more = (k0 + BK) < K;
        if (more) {
#pragma unroll
            for (int i = 0; i < LA; i++) {
                int a = tid + i * THREADS;
                int row = a / (BK / 4), kq = a % (BK / 4);
                nA[i] = *(const float4*)(Ablk + (size_t)row * K + k0 + BK + kq * 4);
            }
#pragma unroll
            for (int i = 0; i < LB; i++) {
                int b = tid + i * THREADS;
                int kr = b / (BN / 4), nq = b % (BN / 4);
                nB[i] = *(const float4*)(Bblk + (size_t)(k0 + BK + kr) * N + nq * 4);
            }
        }

#pragma unroll
        for (int k = 0; k < BK; k++) {
            ull ap[TM / 2];
#pragma unroll
            for (int q = 0; q < TM / 4; q++) {
                F4U t; t.f = *(const float4*)(&As[k][ty*TM + q*4]);
                ap[2*q]   = t.p[0];
                ap[2*q+1] = t.p[1];
            }
            ull bd[TN];
#pragma unroll
            for (int q = 0; q < TN / 4; q++) {
                float4 v = *(const float4*)(&Bs[k][tx*TN + q*4]);
                bd[q*4+0] = pk2(v.x, v.x); bd[q*4+1] = pk2(v.y, v.y);
                bd[q*4+2] = pk2(v.z, v.z); bd[q*4+3] = pk2(v.w, v.w);
            }
#pragma unroll
            for (int r = 0; r < TM / 2; r++)
#pragma unroll
                for (int c = 0; c < TN; c++)
                    ffma2(acc2[r][c], ap[r], bd[c]);
        }

        if (more) {
            __syncthreads();
#pragma unroll
            for (int i = 0; i < LA; i++) {
                int a = tid + i * THREADS;
                int row = a / (BK / 4), kq = a % (BK / 4);
                As[kq*4+0][row] = nA[i].x; As[kq*4+1][row] = nA[i].y;
                As[kq*4+2][row] = nA[i].z; As[kq*4+3][row] = nA[i].w;
            }
#pragma unroll
            for (int i = 0; i < LB; i++) {
                int b = tid + i * THREADS;
                int kr = b / (BN / 4), nq = b % (BN / 4);
                *(float4*)(&Bs[kr][nq*4]) = nB[i];
            }
            __syncthreads();
        }
    }

#pragma unroll
    for (int r2 = 0; r2 < TM / 2; r2++) {
        float s[2][TN];
#pragma unroll
        for (int c = 0; c < TN; c++) upk2(acc2[r2][c], s[0][c], s[1][c]);
#pragma unroll
        for (int h = 0; h < 2; h++) {
            int row = by*BM + ty*TM + 2*r2 + h;
#pragma unroll
            for (int c = 0; c < TN; c += 4) {
                int col = bx*BN + tx*TN + c;
                float4 v;
                v.x = s[h][c+0] + bias[col+0];
                v.y = s[h][c+1] + bias[col+1];
                v.z = s[h][c+2] + bias[col+2];
                v.w = s[h][c+3] + bias[col+3];
                *(float4*)(C + (size_t)row * N + col) = v;
            }
        }
    }
}

// ---------------------------------------------------------------------------
// Fused v2: block = (16 b, 8 u), full m=256 resident.
// ---------------------------------------------------------------------------
#define SM_FLOATS (NB*NU*SP + NU*16*16 + NU*64*16)

__global__ void __launch_bounds__(256) fused_attn(
        const float* __restrict__ attn,   // [B,U,D]
        const float* __restrict__ Ma,     // [M,U,D]
        const float* __restrict__ Mv,     // [M,U,D]
        const float* __restrict__ temp,   // [U]
        float* __restrict__ wout,         // [B,M,U]
        float* __restrict__ outp)         // [B,U,D]
{
    extern __shared__ float sm[];
    float*  sS   = sm;                        // 16*8*264
    float*  sA   = sS + NB*NU*SP;             // [u][d][b] 8*16*16
    float4* sMv4 = (float4*)(sA + NU*16*16);  // swizzled chunk, 2048 float4

    const int b0  = blockIdx.x * NB;
    const int u0  = blockIdx.y * NU;
    const int tid = threadIdx.x;
    const int lane = tid & 31;
    const int wu   = tid >> 5;        // warp <-> u
    const int u    = u0 + wu;

    // ---- stage attn tile -> sA[u][d][b] ----
#pragma unroll
    for (int t = 0; t < 2; t++) {
        int idx = tid + t*256;
        int bi = idx >> 5;
        int uu = (idx >> 2) & 7;
        int dq = idx & 3;
        float4 v = *(const float4*)(attn + ((size_t)(b0+bi)*U_ + u0+uu)*D_ + dq*4);
        sA[(uu*16 + dq*4+0)*16 + bi] = v.x;
        sA[(uu*16 + dq*4+1)*16 + bi] = v.y;
        sA[(uu*16 + dq*4+2)*16 + bi] = v.z;
        sA[(uu*16 + dq*4+3)*16 + bi] = v.w;
    }
    const float tu = temp[u];
    __syncthreads();

    // ---- stage 1: scores ----
    {
        const int tx = lane;
        float4 maq[2][2][4];   // [buf][cc][dq]
#pragma unroll
        for (int cc = 0; cc < 2; cc++) {
            int m = tx + 32*cc;
            const float4* p = (const float4*)(Ma + ((size_t)m*U_ + u)*D_);
#pragma unroll
            for (int dq = 0; dq < 4; dq++) maq[0][cc][dq] = p[dq];
        }
#pragma unroll
        for (int c4 = 0; c4 < 4; c4++) {
            const int buf = c4 & 1;
            if (c4 < 3) {
#pragma unroll
                for (int cc = 0; cc < 2; cc++) {
                    int m = (c4+1)*64 + tx + 32*cc;
                    const float4* p = (const float4*)(Ma + ((size_t)m*U_ + u)*D_);
#pragma unroll
                    for (int dq = 0; dq < 4; dq++) maq[buf ^ 1][cc][dq] = p[dq];
                }
            }
            ull acc[8][2];
#pragma unroll
            for (int bp = 0; bp < 8; bp++) { acc[bp][0] = 0ull; acc[bp][1] = 0ull; }

#pragma unroll
            for (int d = 0; d < 16; d++) {
                ull ap[8];
#pragma unroll
                for (int q = 0; q < 4; q++) {
                    F4U t; t.f = *(const float4*)(&sA[(wu*16 + d)*16 + q*4]);
                    ap[2*q] = t.p[0]; ap[2*q+1] = t.p[1];
                }
                F4U mq0; mq0.f = maq[buf][0][d>>2];
                F4U mq1; mq1.f = maq[buf][1][d>>2];
                ull md0 = pk2(mq0.s[d & 3], mq0.s[d & 3]);
                ull md1 = pk2(mq1.s[d & 3], mq1.s[d & 3]);
#pragma unroll
                for (int bp = 0; bp < 8; bp++) {
                    ffma2(acc[bp][0], ap[bp], md0);
                    ffma2(acc[bp][1], ap[bp], md1);
                }
            }
#pragma unroll
            for (int cc = 0; cc < 2; cc++) {
                int m = c4*64 + tx + 32*cc;
#pragma unroll
                for (int bp = 0; bp < 8; bp++) {
                    float s0, s1;
                    upk2(acc[bp][cc], s0, s1);
                    int bA = 2*bp, bB = 2*bp + 1;
                    sS[(bA*NU + wu)*SP + m] = (m == b0 + bA) ? -INFINITY : s0 * tu;
                    sS[(bB*NU + wu)*SP + m] = (m == b0 + bB) ? -INFINITY : s1 * tu;
                }
            }
        }
    }
    __syncthreads();

    // ---- stage 2: grouped softmax ----
    {
        int g  = tid & 7;
        int uu = (tid >> 3) & 7;
        int bq = tid >> 6;
#pragma unroll
        for (int i = 0; i < 4; i++) {
            int b = bq*4 + i;
            float* row = sS + (b*NU + uu)*SP + g;
            float v[32];
            float mx = -INFINITY;
#pragma unroll
            for (int j = 0; j < 32; j++) { v[j] = row[j*8]; mx = fmaxf(mx, v[j]); }
            float s = 0.f;
#pragma unroll
            for (int j = 0; j < 32; j++) { v[j] = __expf(v[j] - mx); s += v[j]; }
            float inv = 1.f / (8.f * s);
#pragma unroll
            for (int j = 0; j < 32; j++) row[j*8] = v[j] * inv;
        }
    }
    __syncthreads();

    // ---- stage 2b: coalesced weights store [b][m][u0..u0+7] ----
    {
        int b  = tid >> 4;
        int tl = tid & 15;
#pragma unroll
        for (int mi = 0; mi < 16; mi++) {
            int m = tl + 16*mi;
            float w8[8];
#pragma unroll
            for (int uu = 0; uu < 8; uu++) w8[uu] = sS[(b*NU + uu)*SP + m];
            float4* dst = (float4*)(wout + ((size_t)(b0 + b)*M_ + m)*U_ + u0);
            dst[0] = make_float4(w8[0], w8[1], w8[2], w8[3]);
            dst[1] = make_float4(w8[4], w8[5], w8[6], w8[7]);
        }
    }

    // ---- stage 3: outputs, 8b x 8d per thread, m-split 8, shfl reduce ----
    {
        const int mseg = lane & 7;
        const int dg   = (lane >> 3) & 1;
        const int bg   = lane >> 4;

        ull acc[8][4];
#pragma unroll
        for (int bi = 0; bi < 8; bi++)
#pragma unroll
            for (int dp = 0; dp < 4; dp++) acc[bi][dp] = 0ull;

#pragma unroll
        for (int c4 = 0; c4 < 4; c4++) {
            __syncthreads();
#pragma unroll
            for (int t = 0; t < 8; t++) {
                int idx = tid + t*256;
                int mloc = idx >> 5;
                int uu = (idx >> 2) & 7;
                int dq = idx & 3;
                float4 v = *(const float4*)(Mv + ((size_t)(c4*64 + mloc)*U_ + u0+uu)*D_ + dq*4);
                sMv4[uu*256 + mloc*4 + (dq ^ ((mloc >> 3) & 3))] = v;
            }
            __syncthreads();

#pragma unroll
            for (int h = 0; h < 2; h++) {
                int mbase = c4*64 + mseg*8 + h*4;
                F4U w4[8];
#pragma unroll
                for (int bi = 0; bi < 8; bi++)
                    w4[bi].f = *(const float4*)(&sS[((bg*8 + bi)*NU + wu)*SP + mbase]);
                ull mvp[4][4];
#pragma unroll
                for (int mi = 0; mi < 4; mi++) {
#pragma unroll
                    for (int k = 0; k < 2; k++) {
                        int mloc = mseg*8 + h*4 + mi;
                        F4U v; v.f = sMv4[wu*256 + mloc*4 + ((dg*2 + k) ^ (mseg & 3))];
                        mvp[mi][k*2]   = v.p[0];
                        mvp[mi][k*2+1] = v.p[1];
                    }
                }
#pragma unroll
                for (int mi = 0; mi < 4; mi++)
#pragma unroll
                    for (int bi = 0; bi < 8; bi++) {
                        ull wd = pk2(w4[bi].s[mi], w4[bi].s[mi]);
                        ffma2(acc[bi][0], wd, mvp[mi][0]);
                        ffma2(acc[bi][1], wd, mvp[mi][1]);
                        ffma2(acc[bi][2], wd, mvp[mi][2]);
                        ffma2(acc[bi][3], wd, mvp[mi][3]);
                    }
            }
        }

#pragma unroll
        for (int off = 1; off < 8; off <<= 1) {
#pragma unroll
            for (int bi = 0; bi < 8; bi++)
#pragma unroll
                for (int dp = 0; dp < 4; dp++) {
                    ull o = __shfl_xor_sync(0xffffffffu, acc[bi][dp], off);
                    acc[bi][dp] = add2(acc[bi][dp], o);
                }
        }
        if (mseg == 0) {
#pragma unroll
            for (int bi = 0; bi < 8; bi++) {
                float o[8];
                upk2(acc[bi][0], o[0], o[1]);
                upk2(acc[bi][1], o[2], o[3]);
                upk2(acc[bi][2], o[4], o[5]);
                upk2(acc[bi][3], o[6], o[7]);
                float* dst = outp + ((size_t)(b0 + bg*8 + bi)*U_ + u)*D_ + dg*8;
                *(float4*)(dst)     = make_float4(o[0], o[1], o[2], o[3]);
                *(float4*)(dst + 4) = make_float4(o[4], o[5], o[6], o[7]);
            }
        }
    }
}

// ---------------------------------------------------------------------------
extern "C" void kernel_launch(void* const* d_in, const int* in_sizes, int n_in,
                              void* d_out, int out_size)
{
    const float* x    = (const float*)d_in[0];
    const float* W1   = (const float*)d_in[1];
    const float* b1   = (const float*)d_in[2];
    const float* W2   = (const float*)d_in[3];
    const float* b2   = (const float*)d_in[4];
    const float* temp = (const float*)d_in[5];
    const float* Ma   = (const float*)d_in[6];
    const float* Mv   = (const float*)d_in[7];

    float* attn = (float*)d_out;                         // [B,U,D]
    float* wout = attn + (size_t)B_ * U_ * D_;           // [B,M,U]
    float* outp = wout + (size_t)B_ * B_ * U_;           // [B,U,D]

    float* h_ptr = nullptr;
    cudaGetSymbolAddress((void**)&h_ptr, g_h);

    // h = x @ W1 + b1   (TX*TY = 8*16 = 128 threads OK)
    sgemm_bias<64, 32, 16, 4, 4, 128><<<dim3(DG_/32, B_/64), 128>>>(
        x, W1, b1, h_ptr, B_, DG_, DIN_);

    // attention = h @ W2 + b2   (TX*TY = 16*16 = 256 threads OK — round-2 config)
    sgemm_bias<128, 128, 16, 8, 8, 256><<<dim3((U_*D_)/128, B_/128), 256>>>(
        h_ptr, W2, b2, attn, B_, U_*D_, DG_);

    // fused scores + softmax + weights + outputs
    int smem = SM_FLOATS * (int)sizeof(float);
    cudaFuncSetAttribute(fused_attn,
                         cudaFuncAttributeMaxDynamicSharedMemorySize, smem);
    fused_attn<<<dim3(B_/NB, U_/NU), 256, smem>>>(attn, Ma, Mv, temp, wout, outp);
}

// round 5
// speedup vs baseline: 1.3298x; 1.1699x over previous
#include <cuda_runtime.h>
#include <cmath>

#define B_   256
#define DIN_ 1024
#define DG_  1024
#define U_   512
#define D_   16
#define M_   256
#define G_   8

#define NB 16     // b per fused block
#define NU 8      // u per fused block
#define SP 264    // S pitch (floats)

#define KSPLIT 4

__device__ float g_h[B_ * DG_];              // 1 MB: h
__device__ float g_hp[KSPLIT][B_ * DG_];     // 4 MB: split-K partials

// ---------------------------------------------------------------------------
// f32x2 helpers
// ---------------------------------------------------------------------------
typedef unsigned long long ull;
union F4U { float4 f; ull p[2]; float s[4]; };

__device__ __forceinline__ ull pk2(float a, float b) {
    ull r; asm("mov.b64 %0, {%1, %2};" : "=l"(r) : "f"(a), "f"(b)); return r;
}
__device__ __forceinline__ void upk2(ull v, float& a, float& b) {
    asm("mov.b64 {%0, %1}, %2;" : "=f"(a), "=f"(b) : "l"(v));
}
__device__ __forceinline__ void ffma2(ull& d, ull a, ull b) {
    asm("fma.rn.f32x2 %0, %1, %2, %0;" : "+l"(d) : "l"(a), "l"(b));
}
__device__ __forceinline__ ull add2(ull a, ull b) {
    ull r; asm("add.rn.f32x2 %0, %1, %2;" : "=l"(r) : "l"(a), "l"(b)); return r;
}

// ---------------------------------------------------------------------------
// fp32 SGEMM core, packed-pair inner product, optional bias, k-range slice.
// C slice selected by blockIdx.z * sliceStride. (BN/TN)*(BM/TM) == THREADS.
// ---------------------------------------------------------------------------
template<int BM, int BN, int BK, int TM, int TN, int THREADS, bool BIAS>
__global__ void __launch_bounds__(THREADS) sgemm_core(
        const float* __restrict__ A, const float* __restrict__ Bm,
        const float* __restrict__ bias, float* __restrict__ C,
        int N, int K, int kChunk, int sliceStride)
{
    static_assert((BN / TN) * (BM / TM) == THREADS, "thread tiling mismatch");
    __shared__ float As[BK][BM + 4];
    __shared__ float Bs[BK][BN];

    const int tid = threadIdx.x;
    const int bx = blockIdx.x, by = blockIdx.y;
    const int kBegin = blockIdx.z * kChunk;
    const int kEnd   = kBegin + kChunk;
    float* Cs = C + (size_t)blockIdx.z * sliceStride;

    constexpr int TX = BN / TN;
    const int tx = tid % TX;
    const int ty = tid / TX;

    constexpr int LA = (BM * BK / 4) / THREADS;
    constexpr int LB = (BK * BN / 4) / THREADS;
    static_assert(LA >= 1 && LB >= 1, "tile too small");

    ull acc2[TM / 2][TN];
#pragma unroll
    for (int r = 0; r < TM / 2; r++)
#pragma unroll
        for (int c = 0; c < TN; c++) acc2[r][c] = 0ull;

    const float* Ablk = A + (size_t)by * BM * K;
    const float* Bblk = Bm + (size_t)bx * BN;

#pragma unroll
    for (int i = 0; i < LA; i++) {
        int a = tid + i * THREADS;
        int row = a / (BK / 4), kq = a % (BK / 4);
        float4 v = *(const float4*)(Ablk + (size_t)row * K + kBegin + kq * 4);
        As[kq*4+0][row] = v.x; As[kq*4+1][row] = v.y;
        As[kq*4+2][row] = v.z; As[kq*4+3][row] = v.w;
    }
#pragma unroll
    for (int i = 0; i < LB; i++) {
        int b = tid + i * THREADS;
        int kr = b / (BN / 4), nq = b % (BN / 4);
        *(float4*)(&Bs[kr][nq*4]) =
            *(const float4*)(Bblk + (size_t)(kBegin + kr) * N + nq * 4);
    }
    __syncthreads();

    for (int k0 = kBegin; k0 < kEnd; k0 += BK) {
        float4 nA[LA], nB[LB];
        const bool more = (k0 + BK) < kEnd;
        if (more) {
#pragma unroll
            for (int i = 0; i < LA; i++) {
                int a = tid + i * THREADS;
                int row = a / (BK / 4), kq = a % (BK / 4);
                nA[i] = *(const float4*)(Ablk + (size_t)row * K + k0 + BK + kq * 4);
            }
#pragma unroll
            for (int i = 0; i < LB; i++) {
                int b = tid + i * THREADS;
                int kr = b / (BN / 4), nq = b % (BN / 4);
                nB[i] = *(const float4*)(Bblk + (size_t)(k0 + BK + kr) * N + nq * 4);
            }
        }

#pragma unroll
        for (int k = 0; k < BK; k++) {
            ull ap[TM / 2];
#pragma unroll
            for (int q = 0; q < TM / 4; q++) {
                F4U t; t.f = *(const float4*)(&As[k][ty*TM + q*4]);
                ap[2*q]   = t.p[0];
                ap[2*q+1] = t.p[1];
            }
            ull bd[TN];
#pragma unroll
            for (int q = 0; q < TN / 4; q++) {
                float4 v = *(const float4*)(&Bs[k][tx*TN + q*4]);
                bd[q*4+0] = pk2(v.x, v.x); bd[q*4+1] = pk2(v.y, v.y);
                bd[q*4+2] = pk2(v.z, v.z); bd[q*4+3] = pk2(v.w, v.w);
            }
#pragma unroll
            for (int r = 0; r < TM / 2; r++)
#pragma unroll
                for (int c = 0; c < TN; c++)
                    ffma2(acc2[r][c], ap[r], bd[c]);
        }

        if (more) {
            __syncthreads();
#pragma unroll
            for (int i = 0; i < LA; i++) {
                int a = tid + i * THREADS;
                int row = a / (BK / 4), kq = a % (BK / 4);
                As[kq*4+0][row] = nA[i].x; As[kq*4+1][row] = nA[i].y;
                As[kq*4+2][row] = nA[i].z; As[kq*4+3][row] = nA[i].w;
            }
#pragma unroll
            for (int i = 0; i < LB; i++) {
                int b = tid + i * THREADS;
                int kr = b / (BN / 4), nq = b % (BN / 4);
                *(float4*)(&Bs[kr][nq*4]) = nB[i];
            }
            __syncthreads();
        }
    }

#pragma unroll
    for (int r2 = 0; r2 < TM / 2; r2++) {
        float s[2][TN];
#pragma unroll
        for (int c = 0; c < TN; c++) upk2(acc2[r2][c], s[0][c], s[1][c]);
#pragma unroll
        for (int h = 0; h < 2; h++) {
            int row = by*BM + ty*TM + 2*r2 + h;
#pragma unroll
            for (int c = 0; c < TN; c += 4) {
                int col = bx*BN + tx*TN + c;
                float4 v;
                if (BIAS) {
                    v.x = s[h][c+0] + bias[col+0];
                    v.y = s[h][c+1] + bias[col+1];
                    v.z = s[h][c+2] + bias[col+2];
                    v.w = s[h][c+3] + bias[col+3];
                } else {
                    v.x = s[h][c+0]; v.y = s[h][c+1];
                    v.z = s[h][c+2]; v.w = s[h][c+3];
                }
                *(float4*)(Cs + (size_t)row * N + col) = v;
            }
        }
    }
}

// ---------------------------------------------------------------------------
// reduce split-K partials + bias -> g_h   (B_*DG_ = 256K floats = 64K float4)
// ---------------------------------------------------------------------------
__global__ void __launch_bounds__(256) reduce_h(const float* __restrict__ bias)
{
    int i = blockIdx.x * 256 + threadIdx.x;      // float4 index
    int col4 = i & (DG_/4 - 1);
    float4 a = *(const float4*)(&g_hp[0][i*4]);
    float4 b = *(const float4*)(&g_hp[1][i*4]);
    float4 c = *(const float4*)(&g_hp[2][i*4]);
    float4 d = *(const float4*)(&g_hp[3][i*4]);
    float4 bb = *(const float4*)(bias + col4*4);
    float4 o;
    o.x = a.x + b.x + c.x + d.x + bb.x;
    o.y = a.y + b.y + c.y + d.y + bb.y;
    o.z = a.z + b.z + c.z + d.z + bb.z;
    o.w = a.w + b.w + c.w + d.w + bb.w;
    *(float4*)(&g_h[i*4]) = o;
}

// ---------------------------------------------------------------------------
// Fused v2: block = (16 b, 8 u), full m=256 resident.  (unchanged, passing)
// ---------------------------------------------------------------------------
#define SM_FLOATS (NB*NU*SP + NU*16*16 + NU*64*16)

__global__ void __launch_bounds__(256) fused_attn(
        const float* __restrict__ attn,   // [B,U,D]
        const float* __restrict__ Ma,     // [M,U,D]
        const float* __restrict__ Mv,     // [M,U,D]
        const float* __restrict__ temp,   // [U]
        float* __restrict__ wout,         // [B,M,U]
        float* __restrict__ outp)         // [B,U,D]
{
    extern __shared__ float sm[];
    float*  sS   = sm;
    float*  sA   = sS + NB*NU*SP;
    float4* sMv4 = (float4*)(sA + NU*16*16);

    const int b0  = blockIdx.x * NB;
    const int u0  = blockIdx.y * NU;
    const int tid = threadIdx.x;
    const int lane = tid & 31;
    const int wu   = tid >> 5;
    const int u    = u0 + wu;

#pragma unroll
    for (int t = 0; t < 2; t++) {
        int idx = tid + t*256;
        int bi = idx >> 5;
        int uu = (idx >> 2) & 7;
        int dq = idx & 3;
        float4 v = *(const float4*)(attn + ((size_t)(b0+bi)*U_ + u0+uu)*D_ + dq*4);
        sA[(uu*16 + dq*4+0)*16 + bi] = v.x;
        sA[(uu*16 + dq*4+1)*16 + bi] = v.y;
        sA[(uu*16 + dq*4+2)*16 + bi] = v.z;
        sA[(uu*16 + dq*4+3)*16 + bi] = v.w;
    }
    const float tu = temp[u];
    __syncthreads();

    // ---- stage 1: scores ----
    {
        const int tx = lane;
        float4 maq[2][2][4];
#pragma unroll
        for (int cc = 0; cc < 2; cc++) {
            int m = tx + 32*cc;
            const float4* p = (const float4*)(Ma + ((size_t)m*U_ + u)*D_);
#pragma unroll
            for (int dq = 0; dq < 4; dq++) maq[0][cc][dq] = p[dq];
        }
#pragma unroll
        for (int c4 = 0; c4 < 4; c4++) {
            const int buf = c4 & 1;
            if (c4 < 3) {
#pragma unroll
                for (int cc = 0; cc < 2; cc++) {
                    int m = (c4+1)*64 + tx + 32*cc;
                    const float4* p = (const float4*)(Ma + ((size_t)m*U_ + u)*D_);
#pragma unroll
                    for (int dq = 0; dq < 4; dq++) maq[buf ^ 1][cc][dq] = p[dq];
                }
            }
            ull acc[8][2];
#pragma unroll
            for (int bp = 0; bp < 8; bp++) { acc[bp][0] = 0ull; acc[bp][1] = 0ull; }

#pragma unroll
            for (int d = 0; d < 16; d++) {
                ull ap[8];
#pragma unroll
                for (int q = 0; q < 4; q++) {
                    F4U t; t.f = *(const float4*)(&sA[(wu*16 + d)*16 + q*4]);
                    ap[2*q] = t.p[0]; ap[2*q+1] = t.p[1];
                }
                F4U mq0; mq0.f = maq[buf][0][d>>2];
                F4U mq1; mq1.f = maq[buf][1][d>>2];
                ull md0 = pk2(mq0.s[d & 3], mq0.s[d & 3]);
                ull md1 = pk2(mq1.s[d & 3], mq1.s[d & 3]);
#pragma unroll
                for (int bp = 0; bp < 8; bp++) {
                    ffma2(acc[bp][0], ap[bp], md0);
                    ffma2(acc[bp][1], ap[bp], md1);
                }
            }
#pragma unroll
            for (int cc = 0; cc < 2; cc++) {
                int m = c4*64 + tx + 32*cc;
#pragma unroll
                for (int bp = 0; bp < 8; bp++) {
                    float s0, s1;
                    upk2(acc[bp][cc], s0, s1);
                    int bA = 2*bp, bB = 2*bp + 1;
                    sS[(bA*NU + wu)*SP + m] = (m == b0 + bA) ? -INFINITY : s0 * tu;
                    sS[(bB*NU + wu)*SP + m] = (m == b0 + bB) ? -INFINITY : s1 * tu;
                }
            }
        }
    }
    __syncthreads();

    // ---- stage 2: grouped softmax ----
    {
        int g  = tid & 7;
        int uu = (tid >> 3) & 7;
        int bq = tid >> 6;
#pragma unroll
        for (int i = 0; i < 4; i++) {
            int b = bq*4 + i;
            float* row = sS + (b*NU + uu)*SP + g;
            float v[32];
            float mx = -INFINITY;
#pragma unroll
            for (int j = 0; j < 32; j++) { v[j] = row[j*8]; mx = fmaxf(mx, v[j]); }
            float s = 0.f;
#pragma unroll
            for (int j = 0; j < 32; j++) { v[j] = __expf(v[j] - mx); s += v[j]; }
            float inv = 1.f / (8.f * s);
#pragma unroll
            for (int j = 0; j < 32; j++) row[j*8] = v[j] * inv;
        }
    }
    __syncthreads();

    // ---- stage 2b: coalesced weights store ----
    {
        int b  = tid >> 4;
        int tl = tid & 15;
#pragma unroll
        for (int mi = 0; mi < 16; mi++) {
            int m = tl + 16*mi;
            float w8[8];
#pragma unroll
            for (int uu = 0; uu < 8; uu++) w8[uu] = sS[(b*NU + uu)*SP + m];
            float4* dst = (float4*)(wout + ((size_t)(b0 + b)*M_ + m)*U_ + u0);
            dst[0] = make_float4(w8[0], w8[1], w8[2], w8[3]);
            dst[1] = make_float4(w8[4], w8[5], w8[6], w8[7]);
        }
    }

    // ---- stage 3: outputs ----
    {
        const int mseg = lane & 7;
        const int dg   = (lane >> 3) & 1;
        const int bg   = lane >> 4;

        ull acc[8][4];
#pragma unroll
        for (int bi = 0; bi < 8; bi++)
#pragma unroll
            for (int dp = 0; dp < 4; dp++) acc[bi][dp] = 0ull;

#pragma unroll
        for (int c4 = 0; c4 < 4; c4++) {
            __syncthreads();
#pragma unroll
            for (int t = 0; t < 8; t++) {
                int idx = tid + t*256;
                int mloc = idx >> 5;
                int uu = (idx >> 2) & 7;
                int dq = idx & 3;
                float4 v = *(const float4*)(Mv + ((size_t)(c4*64 + mloc)*U_ + u0+uu)*D_ + dq*4);
                sMv4[uu*256 + mloc*4 + (dq ^ ((mloc >> 3) & 3))] = v;
            }
            __syncthreads();

#pragma unroll
            for (int h = 0; h < 2; h++) {
                int mbase = c4*64 + mseg*8 + h*4;
                F4U w4[8];
#pragma unroll
                for (int bi = 0; bi < 8; bi++)
                    w4[bi].f = *(const float4*)(&sS[((bg*8 + bi)*NU + wu)*SP + mbase]);
                ull mvp[4][4];
#pragma unroll
                for (int mi = 0; mi < 4; mi++) {
#pragma unroll
                    for (int k = 0; k < 2; k++) {
                        int mloc = mseg*8 + h*4 + mi;
                        F4U v; v.f = sMv4[wu*256 + mloc*4 + ((dg*2 + k) ^ (mseg & 3))];
                        mvp[mi][k*2]   = v.p[0];
                        mvp[mi][k*2+1] = v.p[1];
                    }
                }
#pragma unroll
                for (int mi = 0; mi < 4; mi++)
#pragma unroll
                    for (int bi = 0; bi < 8; bi++) {
                        ull wd = pk2(w4[bi].s[mi], w4[bi].s[mi]);
                        ffma2(acc[bi][0], wd, mvp[mi][0]);
                        ffma2(acc[bi][1], wd, mvp[mi][1]);
                        ffma2(acc[bi][2], wd, mvp[mi][2]);
                        ffma2(acc[bi][3], wd, mvp[mi][3]);
                    }
            }
        }

#pragma unroll
        for (int off = 1; off < 8; off <<= 1) {
#pragma unroll
            for (int bi = 0; bi < 8; bi++)
#pragma unroll
                for (int dp = 0; dp < 4; dp++) {
                    ull o = __shfl_xor_sync(0xffffffffu, acc[bi][dp], off);
                    acc[bi][dp] = add2(acc[bi][dp], o);
                }
        }
        if (mseg == 0) {
#pragma unroll
            for (int bi = 0; bi < 8; bi++) {
                float o[8];
                upk2(acc[bi][0], o[0], o[1]);
                upk2(acc[bi][1], o[2], o[3]);
                upk2(acc[bi][2], o[4], o[5]);
                upk2(acc[bi][3], o[6], o[7]);
                float* dst = outp + ((size_t)(b0 + bg*8 + bi)*U_ + u)*D_ + dg*8;
                *(float4*)(dst)     = make_float4(o[0], o[1], o[2], o[3]);
                *(float4*)(dst + 4) = make_float4(o[4], o[5], o[6], o[7]);
            }
        }
    }
}

// ---------------------------------------------------------------------------
extern "C" void kernel_launch(void* const* d_in, const int* in_sizes, int n_in,
                              void* d_out, int out_size)
{
    const float* x    = (const float*)d_in[0];
    const float* W1   = (const float*)d_in[1];
    const float* b1   = (const float*)d_in[2];
    const float* W2   = (const float*)d_in[3];
    const float* b2   = (const float*)d_in[4];
    const float* temp = (const float*)d_in[5];
    const float* Ma   = (const float*)d_in[6];
    const float* Mv   = (const float*)d_in[7];

    float* attn = (float*)d_out;                         // [B,U,D]
    float* wout = attn + (size_t)B_ * U_ * D_;           // [B,M,U]
    float* outp = wout + (size_t)B_ * B_ * U_;           // [B,U,D]

    float* h_ptr = nullptr;
    cudaGetSymbolAddress((void**)&h_ptr, g_h);
    float* hp_ptr = nullptr;
    cudaGetSymbolAddress((void**)&hp_ptr, g_hp);

    // h partials: x @ W1 split-K=4  (512 blocks of 128 threads)
    sgemm_core<64, 32, 16, 4, 4, 128, false>
        <<<dim3(DG_/32, B_/64, KSPLIT), 128>>>(
        x, W1, nullptr, hp_ptr, DG_, DIN_, DIN_/KSPLIT, B_*DG_);

    // h = sum partials + b1
    reduce_h<<<(B_*DG_/4)/256, 256>>>(b1);

    // attention = h @ W2 + b2  (256 blocks of 128 threads)
    sgemm_core<128, 64, 16, 8, 8, 128, true>
        <<<dim3((U_*D_)/64, B_/128, 1), 128>>>(
        h_ptr, W2, b2, attn, U_*D_, DG_, DG_, 0);

    // fused scores + softmax + weights + outputs
    int smem = SM_FLOATS * (int)sizeof(float);
    cudaFuncSetAttribute(fused_attn,
                         cudaFuncAttributeMaxDynamicSharedMemorySize, smem);
    fused_attn<<<dim3(B_/NB, U_/NU), 256, smem>>>(attn, Ma, Mv, temp, wout, outp);
}